// round 1
// baseline (speedup 1.0000x reference)
#include <cuda_runtime.h>
#include <cstdint>

// Problem constants: features (B, D, L) f32, tois (B, N, 2) i32, MAX_SPAN=64
#define BB 16
#define DD 256
#define LL 4096
#define NQ 4096
// chunk size for local inclusive scan; must be >= MAX_SPAN
#define CH 64

// Scratch: transposed features and chunk-local inclusive cumsum, layout [B][L][D]
__device__ float g_ft[(size_t)BB * LL * DD];
__device__ float g_ic[(size_t)BB * LL * DD];

// ---------------------------------------------------------------------------
// Kernel 1: tile transpose + chunk-local (64-wide) inclusive scan.
// One block handles (b, 32 d-rows, 64 l-columns). No inter-block dependency:
// the scan restarts at every 64-aligned chunk, which is sufficient because
// spans never exceed 64 (straddle at most one boundary).
// ---------------------------------------------------------------------------
__global__ void __launch_bounds__(256) k_transpose_scan(const float* __restrict__ feat) {
    __shared__ float ftT[64][33];
    __shared__ float icT[64][33];

    const int l0 = blockIdx.x << 6;   // l chunk base (multiple of 64)
    const int d0 = blockIdx.y << 5;   // d base (multiple of 32)
    const int b  = blockIdx.z;
    const int tid  = threadIdx.x;
    const int w    = tid >> 5;
    const int lane = tid & 31;

    // Each warp scans 4 d-rows; each lane loads a contiguous float2 (coalesced 256B/row).
    #pragma unroll
    for (int r = 0; r < 4; r++) {
        const int dd = (w << 2) + r;
        const float2* row = reinterpret_cast<const float2*>(
            feat + ((size_t)b * DD + d0 + dd) * LL + l0);
        float2 v = row[lane];
        float s = v.x + v.y;
        // warp-inclusive scan of pair sums
        #pragma unroll
        for (int o = 1; o < 32; o <<= 1) {
            float t = __shfl_up_sync(0xffffffffu, s, o);
            if (lane >= o) s += t;
        }
        ftT[2 * lane    ][dd] = v.x;
        ftT[2 * lane + 1][dd] = v.y;
        icT[2 * lane    ][dd] = s - v.y;  // inclusive at 2*lane
        icT[2 * lane + 1][dd] = s;        // inclusive at 2*lane+1
    }
    __syncthreads();

    // Coalesced transposed writes: 32 consecutive d per row segment (128B).
    const size_t gb = ((size_t)b * LL + l0) * DD + d0;
    #pragma unroll
    for (int k = 0; k < 8; k++) {
        const int e  = tid + (k << 8);
        const int ll = e >> 5;
        const int dd = e & 31;
        const size_t gi = gb + (size_t)ll * DD + dd;
        g_ft[gi] = ftT[ll][dd];
        g_ic[gi] = icT[ll][dd];
    }
}

// ---------------------------------------------------------------------------
// Kernel 2: one 256-thread block per query (b, n); thread d handles feature d.
// All loads/stores fully coalesced thanks to the [B][L][D] layout.
// ---------------------------------------------------------------------------
__global__ void __launch_bounds__(256) k_pool(const int* __restrict__ tois,
                                              float* __restrict__ out,
                                              int write_counts) {
    const int q = blockIdx.x;          // q = b*N + n
    const int d = threadIdx.x;
    const int b = q >> 12;             // N = 4096

    const int2 t = reinterpret_cast<const int2*>(tois)[q];
    const int start = t.x;
    const int end   = t.y;
    const int e     = end - 1;

    const size_t bl = (size_t)b * LL;

    const float head = g_ft[(bl + start) * DD + d];
    const float tail = g_ft[(bl + e)     * DD + d];

    // span sum from chunk-local inclusive cumsums (span <= 64, chunk = 64)
    float num = g_ic[(bl + e) * DD + d];
    const int c0 = start >> 6;
    const int c1 = e >> 6;
    if (c1 != c0)   num += g_ic[(bl + (c0 << 6) + 63) * DD + d]; // whole tail of start chunk
    if (start & 63) num -= g_ic[(bl + start - 1)      * DD + d];

    const float avg = num / (float)(end - start);

    const size_t o = (size_t)q * (3 * DD);
    out[o + d]          = head;
    out[o + DD + d]     = avg;
    out[o + 2 * DD + d] = tail;

    // counts output: cumsum of per-batch query counts = [N, 2N, ..., B*N]
    if (write_counts && q == 0 && d < BB) {
        out[(size_t)BB * NQ * 3 * DD + d] = (float)((d + 1) * NQ);
    }
}

extern "C" void kernel_launch(void* const* d_in, const int* in_sizes, int n_in,
                              void* d_out, int out_size) {
    const float* feat = (const float*)d_in[0];
    const int*   tois = (const int*)d_in[1];
    float*       out  = (float*)d_out;

    const long long total = (long long)BB * NQ * 3 * DD;  // 50,331,648
    const int write_counts = ((long long)out_size >= total + BB) ? 1 : 0;

    dim3 g1(LL / 64, DD / 32, BB);   // 64 x 8 x 16 = 8192 blocks
    k_transpose_scan<<<g1, 256>>>(feat);
    k_pool<<<BB * NQ, 256>>>(tois, out, write_counts);
}

// round 2
// speedup vs baseline: 1.7629x; 1.7629x over previous
#include <cuda_runtime.h>
#include <cstdint>

// Problem constants: features (B, D, L) f32, tois (B, N, 2) i32, MAX_SPAN=64
#define BB 16
#define DD 256
#define LL 4096
#define NQ 4096

// Scratch: chunk-local (64-wide) inclusive cumsum, transposed layout [B][L][D].
// 16*4096*256*4 = 64 MB -> fits L2 (126 MB), so k_pool gathers are L2 hits.
__device__ float g_ic[(size_t)BB * LL * DD];

// ---------------------------------------------------------------------------
// Kernel 1: tile transpose + chunk-local (64-wide) inclusive scan.
// One block handles (b, 32 d-rows, 64 l-columns). No inter-block dependency:
// the scan restarts at every 64-aligned chunk; spans never exceed 64, so any
// span straddles at most one chunk boundary.
// ---------------------------------------------------------------------------
__global__ void __launch_bounds__(256) k_scan(const float* __restrict__ feat) {
    __shared__ float icT[64][33];

    const int l0 = blockIdx.x << 6;   // l chunk base (multiple of 64)
    const int d0 = blockIdx.y << 5;   // d base (multiple of 32)
    const int b  = blockIdx.z;
    const int tid  = threadIdx.x;
    const int w    = tid >> 5;
    const int lane = tid & 31;

    // Each warp scans 4 d-rows; each lane loads a contiguous float2 (256B/row).
    #pragma unroll
    for (int r = 0; r < 4; r++) {
        const int dd = (w << 2) + r;
        const float2* row = reinterpret_cast<const float2*>(
            feat + ((size_t)b * DD + d0 + dd) * LL + l0);
        float2 v = row[lane];
        float s = v.x + v.y;
        // warp-inclusive scan of pair sums
        #pragma unroll
        for (int o = 1; o < 32; o <<= 1) {
            float t = __shfl_up_sync(0xffffffffu, s, o);
            if (lane >= o) s += t;
        }
        icT[2 * lane    ][dd] = s - v.y;  // inclusive prefix at 2*lane
        icT[2 * lane + 1][dd] = s;        // inclusive prefix at 2*lane+1
    }
    __syncthreads();

    // Coalesced transposed writes: 32 consecutive d per 128B segment.
    const size_t gb = ((size_t)b * LL + l0) * DD + d0;
    #pragma unroll
    for (int k = 0; k < 8; k++) {
        const int e  = tid + (k << 8);
        const int ll = e >> 5;
        const int dd = e & 31;
        g_ic[gb + (size_t)ll * DD + dd] = icT[ll][dd];
    }
}

// ---------------------------------------------------------------------------
// Kernel 2: 4 queries per 256-thread block; 64 threads per query, each thread
// owns a float4 of the d dimension. All accesses are 16B vector ops on rows
// that are contiguous 1KB segments in the [B][L][D] layout.
// ---------------------------------------------------------------------------
__global__ void __launch_bounds__(256) k_pool(const int* __restrict__ tois,
                                              float* __restrict__ out,
                                              int write_counts) {
    const int qq  = threadIdx.x >> 6;                 // query slot 0..3
    const int t64 = threadIdx.x & 63;                 // float4 lane within d
    const int q   = (blockIdx.x << 2) + qq;           // global query id
    const int b   = q >> 12;                          // N = 4096

    const int2 t  = reinterpret_cast<const int2*>(tois)[q];
    const int start = t.x;
    const int e     = t.y - 1;

    const float4* __restrict__ ic = reinterpret_cast<const float4*>(g_ic);
    const size_t rowBase = (size_t)b * LL;            // in rows
    // row l -> float4 index (rowBase + l)*64 + t64
    #define LDROW(l) ic[(rowBase + (size_t)(l)) * 64 + t64]

    const float4 A = LDROW(start);                    // ic[start]
    const float4 C = LDROW(e);                        // ic[e]

    float4 head = A;
    float4 tail = C;
    float4 num  = C;

    if (start & 63) {                                 // uniform per query (2 warps)
        const float4 Bv = LDROW(start - 1);
        head.x = A.x - Bv.x; head.y = A.y - Bv.y;
        head.z = A.z - Bv.z; head.w = A.w - Bv.w;
        num.x -= Bv.x; num.y -= Bv.y; num.z -= Bv.z; num.w -= Bv.w;
    }
    if (e & 63) {
        const float4 Dv = LDROW(e - 1);
        tail.x = C.x - Dv.x; tail.y = C.y - Dv.y;
        tail.z = C.z - Dv.z; tail.w = C.w - Dv.w;
    }
    if ((e >> 6) != (start >> 6)) {                   // span straddles a chunk edge
        const float4 Ev = LDROW((start & ~63) + 63);  // full tail of start chunk
        num.x += Ev.x; num.y += Ev.y; num.z += Ev.z; num.w += Ev.w;
    }
    #undef LDROW

    const float inv = 1.0f / (float)(t.y - start);
    float4 avg;
    avg.x = num.x * inv; avg.y = num.y * inv;
    avg.z = num.z * inv; avg.w = num.w * inv;

    float4* o = reinterpret_cast<float4*>(out + (size_t)q * (3 * DD));
    o[t64]           = head;   // [0,256)
    o[64 + t64]      = avg;    // [256,512)
    o[128 + t64]     = tail;   // [512,768)

    // counts output: cumsum of per-batch query counts = [N, 2N, ..., B*N]
    if (write_counts && q == 0 && t64 < BB && qq == 0) {
        out[(size_t)BB * NQ * 3 * DD + t64] = (float)((t64 + 1) * NQ);
    }
}

extern "C" void kernel_launch(void* const* d_in, const int* in_sizes, int n_in,
                              void* d_out, int out_size) {
    const float* feat = (const float*)d_in[0];
    const int*   tois = (const int*)d_in[1];
    float*       out  = (float*)d_out;

    const long long total = (long long)BB * NQ * 3 * DD;  // 50,331,648
    const int write_counts = ((long long)out_size >= total + BB) ? 1 : 0;

    dim3 g1(LL / 64, DD / 32, BB);    // 64 x 8 x 16 = 8192 blocks
    k_scan<<<g1, 256>>>(feat);
    k_pool<<<(BB * NQ) / 4, 256>>>(tois, out, write_counts);
}